// round 1
// baseline (speedup 1.0000x reference)
#include <cuda_runtime.h>
#include <cstdint>

#define G_   200
#define NPG  500
#define EPG  6000
#define ETOT (G_*EPG)
#define F_   64
#define KPG  250
#define NTH  512
#define NW   (NTH/32)

struct __align__(16) SmemLayout {
    union {
        float x[NPG][F_];                       // 128000 B  (phase 0-1)
        struct {
            float HA[KPG][F_];                  // 64000 B   (GCN lin out / AGNN out)
            float HB[KPG][F_];                  // 64000 B   (GCN out = AGNN in)
            float W1[F_][F_];                   // 16384 B
        } p;
    } u;
    unsigned        col_off[NPG + 1];
    unsigned        cursor[NPG];
    float           dis[NPG];
    float           scorev[NTH];                // scores -> sort keys -> logit_s -> readout partial sums
    int             sidx[NTH];                  // out-deg counts -> sort idx -> readout partial max
    float           d2k[KPG];
    float           ninv[KPG];
    float           b1s[F_];
    float           xstage[NW][F_ + 4];
    float           elog[EPG];                  // also: int scan workspace (phase 0)
    unsigned short  csr_src[EPG];
    unsigned short  klist[KPG];
    short           mapv[NPG];
};

__device__ __forceinline__ float warp_sum(float v) {
    #pragma unroll
    for (int o = 16; o; o >>= 1) v += __shfl_xor_sync(0xffffffffu, v, o);
    return v;
}

__global__ __launch_bounds__(NTH, 1)
void gp_fused_kernel(const float* __restrict__ x,
                     const int*   __restrict__ ei,
                     const float* __restrict__ W1,
                     const float* __restrict__ b1,
                     const float* __restrict__ beta_p,
                     float*       __restrict__ out)
{
    extern __shared__ __align__(16) unsigned char smraw[];
    SmemLayout& S = *reinterpret_cast<SmemLayout*>(smraw);

    const int g    = blockIdx.x;
    const int tid  = threadIdx.x;
    const int wid  = tid >> 5;
    const int lane = tid & 31;
    const int base = g * NPG;
    const int* __restrict__ erow = ei + (size_t)g * EPG;
    const int* __restrict__ ecol = ei + (size_t)ETOT + (size_t)g * EPG;
    const float* __restrict__ xg = x + (size_t)base * F_;

    // ================= Phase 0: stage x, degrees, CSR by col =================
    {   // x tile -> smem (coalesced float4)
        const float4* src = reinterpret_cast<const float4*>(xg);
        float4*       dst = reinterpret_cast<float4*>(&S.u.x[0][0]);
        #pragma unroll 4
        for (int i = tid; i < NPG * F_ / 4; i += NTH) dst[i] = src[i];
    }
    int* icnt = reinterpret_cast<int*>(S.elog);     // in-degree counts (512 ints)
    icnt[tid]  = 0;
    S.sidx[tid] = 0;                                // out-degree counts
    for (int i = tid; i < NPG; i += NTH) S.cursor[i] = 0u;
    __syncthreads();

    for (int e = tid; e < EPG; e += NTH) {
        int r = erow[e] - base;
        int c = ecol[e] - base;
        atomicAdd(&S.sidx[r], 1);
        atomicAdd(&icnt[c],  1);
    }
    __syncthreads();

    for (int n = tid; n < NPG; n += NTH) {
        int d = S.sidx[n];
        S.dis[n] = (d > 0) ? (1.0f / sqrtf((float)d)) : 0.0f;
    }
    // Kogge-Stone inclusive scan of icnt[0..511]
    for (int off = 1; off < NTH; off <<= 1) {
        int v = (tid >= off) ? icnt[tid - off] : 0;
        __syncthreads();
        icnt[tid] += v;
        __syncthreads();
    }
    if (tid <= NPG) S.col_off[tid] = (tid == 0) ? 0u : (unsigned)icnt[tid - 1];
    __syncthreads();

    for (int e = tid; e < EPG; e += NTH) {
        int r = erow[e] - base;
        int c = ecol[e] - base;
        unsigned pos = atomicAdd(&S.cursor[c], 1u);
        S.csr_src[S.col_off[c] + pos] = (unsigned short)r;
    }
    __syncthreads();

    // ================= Phase 1: node information score ======================
    for (int n = wid; n < NPG; n += NW) {
        float xc0 = S.u.x[n][lane], xc1 = S.u.x[n][lane + 32];
        float a0 = 0.f, a1 = 0.f;
        float dn = S.dis[n];
        unsigned kb = S.col_off[n], ke = S.col_off[n + 1];
        for (unsigned k = kb; k < ke; ++k) {
            int s = S.csr_src[k];
            float wgt = S.dis[s] * dn;
            a0 = fmaf(wgt, S.u.x[s][lane],      a0);
            a1 = fmaf(wgt, S.u.x[s][lane + 32], a1);
        }
        float v = fabsf(xc0 - a0) + fabsf(xc1 - a1);
        v = warp_sum(v);
        if (lane == 0) S.scorev[n] = v;
    }
    S.sidx[tid] = tid;
    if (tid >= NPG) S.scorev[tid] = -3.4e38f;
    __syncthreads();

    // ================= Phase 2: bitonic sort desc (score, then idx asc) =====
    for (int k = 2; k <= NTH; k <<= 1) {
        for (int j = k >> 1; j > 0; j >>= 1) {
            __syncthreads();
            int i = tid, ixj = i ^ j;
            if (ixj > i) {
                float si = S.scorev[i], sj = S.scorev[ixj];
                int   ai = S.sidx[i],   aj = S.sidx[ixj];
                bool igt  = (si > sj) || (si == sj && ai < aj);
                bool swp  = ((i & k) == 0) ? (!igt) : igt;
                if (swp) {
                    S.scorev[i] = sj; S.scorev[ixj] = si;
                    S.sidx[i]   = aj; S.sidx[ixj]   = ai;
                }
            }
        }
    }
    __syncthreads();
    for (int n = tid; n < NPG; n += NTH) S.mapv[n] = -1;
    __syncthreads();
    if (tid < KPG) {
        int n = S.sidx[tid];
        S.klist[tid] = (unsigned short)n;
        S.mapv[n]    = (short)tid;
    }
    __syncthreads();

    // ================= Phase 3: GCN =========================================
    {   // W1 -> smem (overwrites x region; matmul re-reads x rows from global)
        const float4* src = reinterpret_cast<const float4*>(W1);
        float4*       dst = reinterpret_cast<float4*>(&S.u.p.W1[0][0]);
        for (int i = tid; i < F_ * F_ / 4; i += NTH) dst[i] = src[i];
    }
    if (tid < F_) S.b1s[tid] = b1[tid];
    const float beta = beta_p[0];
    if (tid < KPG) {                                  // deg2 / d2
        int n = S.klist[tid];
        int cnt = 1;
        for (unsigned k = S.col_off[n]; k < S.col_off[n + 1]; ++k)
            if (S.mapv[S.csr_src[k]] >= 0) cnt++;
        S.d2k[tid] = 1.0f / sqrtf((float)cnt);
    }
    __syncthreads();

    // HA = x_kept @ W1   (warp per row)
    for (int i = wid; i < KPG; i += NW) {
        int n = S.klist[i];
        const float* xr = xg + (size_t)n * F_;
        S.xstage[wid][lane]      = xr[lane];
        S.xstage[wid][lane + 32] = xr[lane + 32];
        __syncwarp();
        float acc0 = 0.f, acc1 = 0.f;
        #pragma unroll
        for (int k2 = 0; k2 < F_; ++k2) {
            float xv = S.xstage[wid][k2];
            acc0 = fmaf(xv, S.u.p.W1[k2][lane],      acc0);
            acc1 = fmaf(xv, S.u.p.W1[k2][lane + 32], acc1);
        }
        S.u.p.HA[i][lane]      = acc0;
        S.u.p.HA[i][lane + 32] = acc1;
        __syncwarp();
    }
    __syncthreads();

    // HB = relu( norm-agg(HA) + d2^2 * HA + b1 )
    for (int i = wid; i < KPG; i += NW) {
        int n = S.klist[i];
        float d2c  = S.d2k[i];
        float self = d2c * d2c;
        float acc0 = self * S.u.p.HA[i][lane];
        float acc1 = self * S.u.p.HA[i][lane + 32];
        for (unsigned k = S.col_off[n]; k < S.col_off[n + 1]; ++k) {
            int rs = S.mapv[S.csr_src[k]];
            if (rs >= 0) {
                float nm = S.d2k[rs] * d2c;
                acc0 = fmaf(nm, S.u.p.HA[rs][lane],      acc0);
                acc1 = fmaf(nm, S.u.p.HA[rs][lane + 32], acc1);
            }
        }
        acc0 += S.b1s[lane];
        acc1 += S.b1s[lane + 32];
        S.u.p.HB[i][lane]      = fmaxf(acc0, 0.f);
        S.u.p.HB[i][lane + 32] = fmaxf(acc1, 0.f);
    }
    __syncthreads();

    // ================= Phase 4: AGNN edge softmax ===========================
    for (int i = wid; i < KPG; i += NW) {     // norms + self logits
        float h0 = S.u.p.HB[i][lane], h1 = S.u.p.HB[i][lane + 32];
        float ss = warp_sum(h0 * h0 + h1 * h1);
        float ni = 1.0f / fmaxf(sqrtf(ss), 1e-12f);
        if (lane == 0) {
            S.ninv[i]   = ni;
            S.scorev[i] = beta * ss * ni * ni;      // logit_s
        }
    }
    __syncthreads();

    for (int i = wid; i < KPG; i += NW) {
        int n = S.klist[i];
        float ni = S.ninv[i];
        float h0 = S.u.p.HB[i][lane], h1 = S.u.p.HB[i][lane + 32];
        float ls = S.scorev[i];
        float m  = ls;
        unsigned kb = S.col_off[n], ke = S.col_off[n + 1];
        for (unsigned k = kb; k < ke; ++k) {        // pass 1: logits + max
            int rs = S.mapv[S.csr_src[k]];
            if (rs >= 0) {
                float d = fmaf(h0, S.u.p.HB[rs][lane],
                           h1 * S.u.p.HB[rs][lane + 32]);
                d = warp_sum(d);
                float lg = beta * d * ni * S.ninv[rs];
                if (lane == 0) S.elog[k] = lg;
                m = fmaxf(m, lg);
            }
        }
        __syncwarp();
        float es    = __expf(ls - m);
        float denom = es;
        float acc0 = es * h0, acc1 = es * h1;
        for (unsigned k = kb; k < ke; ++k) {        // pass 2: weighted sum
            int rs = S.mapv[S.csr_src[k]];
            if (rs >= 0) {
                float e = __expf(S.elog[k] - m);
                denom += e;
                acc0 = fmaf(e, S.u.p.HB[rs][lane],      acc0);
                acc1 = fmaf(e, S.u.p.HB[rs][lane + 32], acc1);
            }
        }
        float inv = 1.0f / denom;
        S.u.p.HA[i][lane]      = acc0 * inv;
        S.u.p.HA[i][lane + 32] = acc1 * inv;
    }
    __syncthreads();

    // ================= Phase 5: readout (mean | max), relu ==================
    {
        int f    = tid & (F_ - 1);
        int part = tid >> 6;                        // 8 partitions
        float a  = 0.f, mx = -3.4e38f;
        for (int i = part; i < KPG; i += 8) {
            float v = S.u.p.HA[i][f];
            a += v;
            mx = fmaxf(mx, v);
        }
        S.scorev[tid] = a;
        reinterpret_cast<float*>(S.sidx)[tid] = mx;
        __syncthreads();
        if (tid < F_) {
            float s = 0.f, m2 = -3.4e38f;
            #pragma unroll
            for (int p = 0; p < 8; ++p) {
                s  += S.scorev[p * F_ + tid];
                m2  = fmaxf(m2, reinterpret_cast<float*>(S.sidx)[p * F_ + tid]);
            }
            out[(size_t)g * (2 * F_) + tid]      = fmaxf(s * (1.0f / (float)KPG), 0.f);
            out[(size_t)g * (2 * F_) + F_ + tid] = fmaxf(m2, 0.f);
        }
    }
}

extern "C" void kernel_launch(void* const* d_in, const int* in_sizes, int n_in,
                              void* d_out, int out_size)
{
    const float* x    = (const float*)d_in[0];
    const int*   ei   = (const int*)  d_in[1];
    const float* W1   = (const float*)d_in[2];
    const float* b1   = (const float*)d_in[3];
    const float* beta = (const float*)d_in[4];
    float*       out  = (float*)d_out;

    int smem = (int)sizeof(SmemLayout);
    cudaFuncSetAttribute(gp_fused_kernel,
                         cudaFuncAttributeMaxDynamicSharedMemorySize, smem);
    gp_fused_kernel<<<G_, NTH, smem>>>(x, ei, W1, b1, beta, out);
}

// round 2
// speedup vs baseline: 1.4391x; 1.4391x over previous
#include <cuda_runtime.h>
#include <cstdint>

#define G_   200
#define NPG  500
#define EPG  6000
#define ETOT (G_*EPG)
#define F_   64
#define FP   66          // padded row (floats) for HA/HB
#define KPG  250
#define NTH  512
#define NW   (NTH/32)

struct __align__(16) SmemLayout {
    union {
        float x[NPG][F_];                       // 128000 B  (phase 0-1)
        struct {
            float HA[KPG][FP];                  // 66000 B
            float HB[KPG][FP];                  // 66000 B
            float W1[F_][F_];                   // 16384 B
        } p;
    } u;                                        // 148384 B
    unsigned        col_off[NPG + 2];
    unsigned        cursor[NPG];
    float           dis[NPG];
    float           scorev[NTH];                // icnt -> sort keys -> vcnt scan -> logit_s
    int             sidx[NTH];                  // out-deg -> sort idx
    float           d2k[KPG];
    float           ninv[KPG];
    float           b1s[F_];
    float           xstage[NW][2][F_];
    float           elogw[NW][64];
    unsigned        kcsr_off[KPG + 2];
    float           rsum[NW][F_];
    float           rmax[NW][F_];
    unsigned short  csr_src[EPG];
    unsigned short  kcsr[EPG];
    unsigned short  klist[KPG];
    short           mapv[NPG];
};

__device__ __forceinline__ float warp_sum(float v) {
    #pragma unroll
    for (int o = 16; o; o >>= 1) v += __shfl_xor_sync(0xffffffffu, v, o);
    return v;
}
__device__ __forceinline__ float warp_max(float v) {
    #pragma unroll
    for (int o = 16; o; o >>= 1) v = fmaxf(v, __shfl_xor_sync(0xffffffffu, v, o));
    return v;
}

__global__ __launch_bounds__(NTH, 1)
void gp_fused_kernel(const float* __restrict__ x,
                     const int*   __restrict__ ei,
                     const float* __restrict__ W1,
                     const float* __restrict__ b1,
                     const float* __restrict__ beta_p,
                     float*       __restrict__ out)
{
    extern __shared__ __align__(16) unsigned char smraw[];
    SmemLayout& S = *reinterpret_cast<SmemLayout*>(smraw);

    const int g    = blockIdx.x;
    const int tid  = threadIdx.x;
    const int wid  = tid >> 5;
    const int lane = tid & 31;
    const int base = g * NPG;
    const int* __restrict__ erow = ei + (size_t)g * EPG;
    const int* __restrict__ ecol = ei + (size_t)ETOT + (size_t)g * EPG;
    const float* __restrict__ xg = x + (size_t)base * F_;

    // ================= Phase 0: stage x, degrees, CSR by col =================
    {
        const float4* src = reinterpret_cast<const float4*>(xg);
        float4*       dst = reinterpret_cast<float4*>(&S.u.x[0][0]);
        #pragma unroll 4
        for (int i = tid; i < NPG * F_ / 4; i += NTH) dst[i] = src[i];
    }
    int* icnt = reinterpret_cast<int*>(S.scorev);
    icnt[tid]   = 0;
    S.sidx[tid] = 0;
    for (int i = tid; i < NPG; i += NTH) S.cursor[i] = 0u;
    __syncthreads();

    for (int e = tid; e < EPG; e += NTH) {
        int r = erow[e] - base;
        int c = ecol[e] - base;
        atomicAdd(&S.sidx[r], 1);
        atomicAdd(&icnt[c],  1);
    }
    __syncthreads();

    for (int n = tid; n < NPG; n += NTH) {
        int d = S.sidx[n];
        S.dis[n] = (d > 0) ? (1.0f / sqrtf((float)d)) : 0.0f;
    }
    for (int off = 1; off < NTH; off <<= 1) {        // Kogge-Stone inclusive scan
        int v = (tid >= off) ? icnt[tid - off] : 0;
        __syncthreads();
        icnt[tid] += v;
        __syncthreads();
    }
    if (tid <= NPG) S.col_off[tid] = (tid == 0) ? 0u : (unsigned)icnt[tid - 1];
    __syncthreads();

    for (int e = tid; e < EPG; e += NTH) {
        int r = erow[e] - base;
        int c = ecol[e] - base;
        unsigned pos = atomicAdd(&S.cursor[c], 1u);
        S.csr_src[S.col_off[c] + pos] = (unsigned short)r;
    }
    __syncthreads();

    // ================= Phase 1: node information score (float2) ============
    const float2* x2 = reinterpret_cast<const float2*>(&S.u.x[0][0]);
    for (int n = wid; n < NPG; n += NW) {
        float2 xc = x2[n * 32 + lane];
        float2 a  = make_float2(0.f, 0.f);
        float  dn = S.dis[n];
        unsigned kb = S.col_off[n], ke = S.col_off[n + 1];
        for (unsigned k = kb; k < ke; ++k) {
            int s = S.csr_src[k];
            float w = S.dis[s] * dn;
            float2 xs = x2[s * 32 + lane];
            a.x = fmaf(w, xs.x, a.x);
            a.y = fmaf(w, xs.y, a.y);
        }
        float v = warp_sum(fabsf(xc.x - a.x) + fabsf(xc.y - a.y));
        if (lane == 0) S.scorev[n] = v;
    }
    S.sidx[tid] = tid;
    if (tid >= NPG) S.scorev[tid] = -3.4e38f;

    // ================= Phase 2: bitonic sort desc (score, then idx asc) =====
    for (int k = 2; k <= NTH; k <<= 1) {
        for (int j = k >> 1; j > 0; j >>= 1) {
            __syncthreads();
            int i = tid, ixj = i ^ j;
            if (ixj > i) {
                float si = S.scorev[i], sj = S.scorev[ixj];
                int   ai = S.sidx[i],   aj = S.sidx[ixj];
                bool igt = (si > sj) || (si == sj && ai < aj);
                bool swp = ((i & k) == 0) ? (!igt) : igt;
                if (swp) {
                    S.scorev[i] = sj; S.scorev[ixj] = si;
                    S.sidx[i]   = aj; S.sidx[ixj]   = ai;
                }
            }
        }
    }
    __syncthreads();
    for (int n = tid; n < NPG; n += NTH) S.mapv[n] = -1;
    __syncthreads();
    if (tid < KPG) {
        int n = S.sidx[tid];
        S.klist[tid] = (unsigned short)n;
        S.mapv[n]    = (short)tid;
    }
    __syncthreads();

    // ================= Phase 3a: W1/b1, deg2, compact kept-CSR ==============
    {   // W1 -> smem (overwrites x region; x re-read from global in matmul)
        const float4* src = reinterpret_cast<const float4*>(W1);
        float4*       dst = reinterpret_cast<float4*>(&S.u.p.W1[0][0]);
        for (int i = tid; i < F_ * F_ / 4; i += NTH) dst[i] = src[i];
    }
    if (tid < F_) S.b1s[tid] = b1[tid];
    const float beta = beta_p[0];

    int* vc = reinterpret_cast<int*>(S.scorev);     // valid-in-edge counts
    vc[tid] = 0;
    __syncthreads();
    if (tid < KPG) {
        int n = S.klist[tid];
        int cnt = 0;
        for (unsigned k = S.col_off[n]; k < S.col_off[n + 1]; ++k)
            if (S.mapv[S.csr_src[k]] >= 0) cnt++;
        S.d2k[tid] = 1.0f / sqrtf((float)(cnt + 1));
        vc[tid]    = cnt;
    }
    __syncthreads();
    for (int off = 1; off < NTH; off <<= 1) {
        int v = (tid >= off) ? vc[tid - off] : 0;
        __syncthreads();
        vc[tid] += v;
        __syncthreads();
    }
    if (tid <= KPG) S.kcsr_off[tid] = (tid == 0) ? 0u : (unsigned)vc[tid - 1];
    __syncthreads();
    if (tid < KPG) {
        int n = S.klist[tid];
        unsigned pos = S.kcsr_off[tid];
        for (unsigned k = S.col_off[n]; k < S.col_off[n + 1]; ++k) {
            int rs = S.mapv[S.csr_src[k]];
            if (rs >= 0) S.kcsr[pos++] = (unsigned short)rs;
        }
    }
    __syncthreads();

    // ================= Phase 3b: HA = x_kept @ W1 (2 rows / warp iter) ======
    const float2* W2  = reinterpret_cast<const float2*>(&S.u.p.W1[0][0]);
    float2* HA2 = reinterpret_cast<float2*>(&S.u.p.HA[0][0]);   // stride FP/2=33
    float2* HB2 = reinterpret_cast<float2*>(&S.u.p.HB[0][0]);
    for (int i0 = wid; i0 < KPG; i0 += 2 * NW) {
        int i1 = i0 + NW;
        bool has1 = (i1 < KPG);
        {
            const float2* xr0 = reinterpret_cast<const float2*>(xg + (size_t)S.klist[i0] * F_);
            reinterpret_cast<float2*>(S.xstage[wid][0])[lane] = xr0[lane];
            if (has1) {
                const float2* xr1 = reinterpret_cast<const float2*>(xg + (size_t)S.klist[i1] * F_);
                reinterpret_cast<float2*>(S.xstage[wid][1])[lane] = xr1[lane];
            }
        }
        __syncwarp();
        float2 a0 = make_float2(0.f, 0.f), a1 = make_float2(0.f, 0.f);
        #pragma unroll
        for (int k2 = 0; k2 < F_; ++k2) {
            float2 w = W2[k2 * 32 + lane];
            float xv0 = S.xstage[wid][0][k2];
            float xv1 = S.xstage[wid][1][k2];
            a0.x = fmaf(xv0, w.x, a0.x);  a0.y = fmaf(xv0, w.y, a0.y);
            a1.x = fmaf(xv1, w.x, a1.x);  a1.y = fmaf(xv1, w.y, a1.y);
        }
        HA2[i0 * 33 + lane] = a0;
        if (has1) HA2[i1 * 33 + lane] = a1;
        __syncwarp();
    }
    __syncthreads();

    // ================= Phase 3c: HB = relu(agg + self + b1) =================
    {
        float2 b2 = reinterpret_cast<const float2*>(S.b1s)[lane];
        for (int i = wid; i < KPG; i += NW) {
            float d2c  = S.d2k[i];
            float self = d2c * d2c;
            float2 ha  = HA2[i * 33 + lane];
            float2 acc = make_float2(self * ha.x, self * ha.y);
            unsigned kb = S.kcsr_off[i], ke = S.kcsr_off[i + 1];
            for (unsigned k = kb; k < ke; ++k) {
                int rs = S.kcsr[k];
                float nm = S.d2k[rs] * d2c;
                float2 hv = HA2[rs * 33 + lane];
                acc.x = fmaf(nm, hv.x, acc.x);
                acc.y = fmaf(nm, hv.y, acc.y);
            }
            acc.x += b2.x; acc.y += b2.y;
            HB2[i * 33 + lane] = make_float2(fmaxf(acc.x, 0.f), fmaxf(acc.y, 0.f));
        }
    }
    __syncthreads();

    // ================= Phase 4a: norms + self logits ========================
    for (int i = wid; i < KPG; i += NW) {
        float2 h = HB2[i * 33 + lane];
        float ss = warp_sum(h.x * h.x + h.y * h.y);
        float ni = 1.0f / fmaxf(sqrtf(ss), 1e-12f);
        if (lane == 0) {
            S.ninv[i]   = ni;
            S.scorev[i] = beta * ss * ni * ni;          // logit_s
        }
    }
    __syncthreads();

    // ================= Phase 4b: AGNN softmax + fused readout ===============
    float2 msum = make_float2(0.f, 0.f);
    float2 mmax = make_float2(-3.4e38f, -3.4e38f);
    for (int i = wid; i < KPG; i += NW) {
        unsigned kb = S.kcsr_off[i];
        int dv = (int)(S.kcsr_off[i + 1] - kb);
        if (dv > 64) dv = 64;
        float ni = S.ninv[i];
        // ---- lane-per-edge dot products -> logits buffer ----
        for (int c = 0; c < dv; c += 32) {
            int e = c + lane;
            float lg = -1e9f;
            if (e < dv) {
                int rs = S.kcsr[kb + e];
                float acc = 0.f;
                #pragma unroll
                for (int f2 = 0; f2 < 32; ++f2) {
                    float2 hn = HB2[i * 33 + f2];       // broadcast
                    float2 hs = HB2[rs * 33 + f2];
                    acc = fmaf(hn.x, hs.x, acc);
                    acc = fmaf(hn.y, hs.y, acc);
                }
                lg = beta * acc * ni * S.ninv[rs];
            }
            if (e < 64) S.elogw[wid][e] = lg;
        }
        __syncwarp();
        // ---- stable softmax + feature-parallel aggregation ----
        float ls = S.scorev[i];
        float m  = ls;
        for (int k = lane; k < dv; k += 32) m = fmaxf(m, S.elogw[wid][k]);
        m = warp_max(m);
        float es    = __expf(ls - m);
        float2 hn   = HB2[i * 33 + lane];
        float denom = es;
        float2 acc  = make_float2(es * hn.x, es * hn.y);
        for (int k = 0; k < dv; ++k) {
            float e2 = __expf(S.elogw[wid][k] - m);
            int rs   = S.kcsr[kb + k];
            float2 hs = HB2[rs * 33 + lane];
            denom += e2;
            acc.x = fmaf(e2, hs.x, acc.x);
            acc.y = fmaf(e2, hs.y, acc.y);
        }
        float inv = 1.0f / denom;
        float2 o = make_float2(acc.x * inv, acc.y * inv);
        msum.x += o.x;  msum.y += o.y;
        mmax.x = fmaxf(mmax.x, o.x);
        mmax.y = fmaxf(mmax.y, o.y);
    }
    reinterpret_cast<float2*>(S.rsum[wid])[lane] = msum;
    reinterpret_cast<float2*>(S.rmax[wid])[lane] = mmax;
    __syncthreads();

    // ================= Phase 5: cross-warp readout reduce ===================
    if (tid < 2 * F_) {
        int f = tid & (F_ - 1);
        if (tid < F_) {
            float s = 0.f;
            #pragma unroll
            for (int w = 0; w < NW; ++w) s += S.rsum[w][f];
            out[(size_t)g * (2 * F_) + f] = fmaxf(s * (1.0f / (float)KPG), 0.f);
        } else {
            float m2 = -3.4e38f;
            #pragma unroll
            for (int w = 0; w < NW; ++w) m2 = fmaxf(m2, S.rmax[w][f]);
            out[(size_t)g * (2 * F_) + F_ + f] = fmaxf(m2, 0.f);
        }
    }
}

extern "C" void kernel_launch(void* const* d_in, const int* in_sizes, int n_in,
                              void* d_out, int out_size)
{
    const float* x    = (const float*)d_in[0];
    const int*   ei   = (const int*)  d_in[1];
    const float* W1   = (const float*)d_in[2];
    const float* b1   = (const float*)d_in[3];
    const float* beta = (const float*)d_in[4];
    float*       out  = (float*)d_out;

    int smem = (int)sizeof(SmemLayout);
    cudaFuncSetAttribute(gp_fused_kernel,
                         cudaFuncAttributeMaxDynamicSharedMemorySize, smem);
    gp_fused_kernel<<<G_, NTH, smem>>>(x, ei, W1, b1, beta, out);
}

// round 4
// speedup vs baseline: 1.5829x; 1.0999x over previous
#include <cuda_runtime.h>
#include <cstdint>

#define G_   200
#define NPG  500
#define EPG  6000
#define ETOT (G_*EPG)
#define F_   64
#define KPG  250
#define NTH  512
#define NW   (NTH/32)

struct __align__(16) SmemLayout {
    float           arena[NPG * 32];            // 64000B: xhalf[500][32] (P1) / HB[250][64] (P3+)
    float           W1s[F_][F_];                // 16384B
    unsigned short  csr_src[EPG];               // 12000B; overlaid by rsum/rmax at readout
    unsigned        col_off[NPG + 4];           // exclusive starts -> (post-scatter) ends
    float           dis[NPG];
    float           scorev[NTH];                // icnt(P0) -> scores(P1/P2) -> logit_s(P4)
    int             sidx[NTH];                  // outdeg(P0) -> sort idx(P2)
    int             wsum[32];
    unsigned short  klist[KPG + 2];
    short           mapv[NPG];
    float           d2k[KPG];
    float           ninv[KPG];
    unsigned short  vcnt[KPG + 2];
    float           b1s[F_];
    float           zst[NW][2][F_];             // 8192B matmul z staging
};

__device__ __forceinline__ float warp_sum(float v) {
    #pragma unroll
    for (int o = 16; o; o >>= 1) v += __shfl_xor_sync(0xffffffffu, v, o);
    return v;
}

__global__ __launch_bounds__(NTH, 2)
void gp_fused_kernel(const float* __restrict__ x,
                     const int*   __restrict__ ei,
                     const float* __restrict__ W1,
                     const float* __restrict__ b1,
                     const float* __restrict__ beta_p,
                     float*       __restrict__ out)
{
    extern __shared__ __align__(16) unsigned char smraw[];
    SmemLayout& S = *reinterpret_cast<SmemLayout*>(smraw);

    const int g    = blockIdx.x;
    const int tid  = threadIdx.x;
    const int wid  = tid >> 5;
    const int lane = tid & 31;
    const int base = g * NPG;
    const int* __restrict__ erow = ei + (size_t)g * EPG;
    const int* __restrict__ ecol = ei + (size_t)ETOT + (size_t)g * EPG;
    const float* __restrict__ xg = x + (size_t)base * F_;

    // ================= Phase 0: degrees + CSR(dst) build ====================
    int* icnt = reinterpret_cast<int*>(S.scorev);   // in-degree counts
    icnt[tid]   = 0;
    S.sidx[tid] = 0;                                // out-degree counts
    __syncthreads();

    for (int e = tid; e < EPG; e += NTH) {
        int r = erow[e] - base;
        int c = ecol[e] - base;
        atomicAdd(&S.sidx[r], 1);
        atomicAdd(&icnt[c],  1);
    }
    __syncthreads();

    // dis from out-degree
    for (int n = tid; n < NPG; n += NTH) {
        int d = S.sidx[n];
        S.dis[n] = (d > 0) ? (1.0f / sqrtf((float)d)) : 0.0f;
    }
    // hierarchical exclusive scan of icnt[0..511] -> col_off starts
    {
        int v = icnt[tid];
        int inc = v;
        #pragma unroll
        for (int o = 1; o < 32; o <<= 1) {
            int u = __shfl_up_sync(0xffffffffu, inc, o);
            if (lane >= o) inc += u;
        }
        if (lane == 31) S.wsum[wid] = inc;
        __syncthreads();
        if (tid < 16) {
            int s = S.wsum[tid];
            #pragma unroll
            for (int o = 1; o < 16; o <<= 1) {
                int u = __shfl_up_sync(0x0000ffffu, s, o);
                if (tid >= o) s += u;
            }
            S.wsum[tid] = s;
        }
        __syncthreads();
        int pre = (wid > 0) ? S.wsum[wid - 1] : 0;
        if (tid < NPG + 1) S.col_off[tid] = (unsigned)(inc - v + pre);  // exclusive
    }
    __syncthreads();

    // scatter: col_off doubles as cursor; afterwards col_off[c] = end(c)
    for (int e = tid; e < EPG; e += NTH) {
        int r = erow[e] - base;
        int c = ecol[e] - base;
        unsigned pos = atomicAdd(&S.col_off[c], 1u);
        S.csr_src[pos] = (unsigned short)r;
    }
    __syncthreads();
    // segment(n) = [ (n? col_off[n-1] : 0), col_off[n] )

    // ================= Phase 1: score, two 32-feature passes ================
    #pragma unroll
    for (int pass = 0; pass < 2; ++pass) {
        // stage xhalf[500][32]
        for (int i = tid; i < NPG * 32; i += NTH) {
            int n = i >> 5, f = i & 31;
            S.arena[i] = xg[n * F_ + pass * 32 + f];
        }
        __syncthreads();
        for (int n = wid; n < NPG; n += NW) {
            float xc = S.arena[n * 32 + lane];
            float a  = 0.f;
            float dn = S.dis[n];
            unsigned kb = n ? S.col_off[n - 1] : 0u;
            unsigned ke = S.col_off[n];
            for (unsigned k = kb; k < ke; ++k) {
                int s = S.csr_src[k];
                a = fmaf(S.dis[s] * dn, S.arena[s * 32 + lane], a);
            }
            float v = warp_sum(fabsf(xc - a));
            if (lane == 0) {
                if (pass == 0) S.scorev[n] = v;
                else           S.scorev[n] += v;
            }
        }
        __syncthreads();
    }
    S.sidx[tid] = tid;
    if (tid >= NPG) S.scorev[tid] = -3.4e38f;

    // ================= Phase 2: bitonic sort desc (score, idx asc) ==========
    for (int k = 2; k <= NTH; k <<= 1) {
        for (int j = k >> 1; j > 0; j >>= 1) {
            __syncthreads();
            int i = tid, ixj = i ^ j;
            if (ixj > i) {
                float si = S.scorev[i], sj = S.scorev[ixj];
                int   ai = S.sidx[i],   aj = S.sidx[ixj];
                bool igt = (si > sj) || (si == sj && ai < aj);
                bool swp = ((i & k) == 0) ? (!igt) : igt;
                if (swp) {
                    S.scorev[i] = sj; S.scorev[ixj] = si;
                    S.sidx[i]   = aj; S.sidx[ixj]   = ai;
                }
            }
        }
    }
    __syncthreads();
    for (int n = tid; n < NPG; n += NTH) S.mapv[n] = -1;
    __syncthreads();
    if (tid < KPG) {
        int n = S.sidx[tid];
        S.klist[tid] = (unsigned short)n;
        S.mapv[n]    = (short)tid;
    }
    __syncthreads();

    // ====== Phase 3a: W1/b1 stage, in-place CSR compaction, d2 ==============
    {
        const float4* src = reinterpret_cast<const float4*>(W1);
        float4*       dst = reinterpret_cast<float4*>(&S.W1s[0][0]);
        for (int i = tid; i < F_ * F_ / 4; i += NTH) dst[i] = src[i];
    }
    if (tid < F_) S.b1s[tid] = b1[tid];
    const float beta = beta_p[0];

    if (tid < KPG) {
        int n = S.klist[tid];
        unsigned kb = n ? S.col_off[n - 1] : 0u;
        unsigned ke = S.col_off[n];
        unsigned w  = kb;
        for (unsigned k = kb; k < ke; ++k) {
            short m = S.mapv[S.csr_src[k]];
            if (m >= 0) S.csr_src[w++] = (unsigned short)m;   // store kept-index
        }
        int cnt = (int)(w - kb);
        S.vcnt[tid] = (unsigned short)cnt;
        S.d2k[tid]  = 1.0f / sqrtf((float)(cnt + 1));
    }
    __syncthreads();

    // ====== Phase 3b: z = d2^2 x_i + sum nm x_j (global gather), HB = relu(zW1+b)
    float2* HB2 = reinterpret_cast<float2*>(S.arena);           // [250][32] float2
    const float2* W2 = reinterpret_cast<const float2*>(&S.W1s[0][0]);
    {
        float2 b2 = reinterpret_cast<const float2*>(S.b1s)[lane];
        for (int i0 = 2 * wid; i0 < KPG; i0 += 2 * NW) {
            #pragma unroll
            for (int r = 0; r < 2; ++r) {
                int i = i0 + r;
                if (i >= KPG) break;
                int n = S.klist[i];
                float d2c = S.d2k[i];
                const float2* xr = reinterpret_cast<const float2*>(xg + (size_t)n * F_);
                float2 xv = xr[lane];
                float  sf = d2c * d2c;
                float2 z  = make_float2(sf * xv.x, sf * xv.y);
                unsigned kb = n ? S.col_off[n - 1] : 0u;
                unsigned ke = kb + S.vcnt[i];
                for (unsigned k = kb; k < ke; ++k) {
                    int rs = S.csr_src[k];
                    float nm = S.d2k[rs] * d2c;
                    const float2* xj = reinterpret_cast<const float2*>(
                        xg + (size_t)S.klist[rs] * F_);
                    float2 xw = xj[lane];
                    z.x = fmaf(nm, xw.x, z.x);
                    z.y = fmaf(nm, xw.y, z.y);
                }
                reinterpret_cast<float2*>(S.zst[wid][r])[lane] = z;
            }
            __syncwarp();
            float2 a0 = b2, a1 = b2;
            #pragma unroll
            for (int k2 = 0; k2 < F_; ++k2) {
                float2 w = W2[k2 * 32 + lane];
                float z0 = S.zst[wid][0][k2];
                float z1 = S.zst[wid][1][k2];
                a0.x = fmaf(z0, w.x, a0.x);  a0.y = fmaf(z0, w.y, a0.y);
                a1.x = fmaf(z1, w.x, a1.x);  a1.y = fmaf(z1, w.y, a1.y);
            }
            HB2[i0 * 32 + lane] = make_float2(fmaxf(a0.x, 0.f), fmaxf(a0.y, 0.f));
            if (i0 + 1 < KPG)
                HB2[(i0 + 1) * 32 + lane] = make_float2(fmaxf(a1.x, 0.f), fmaxf(a1.y, 0.f));
            __syncwarp();
        }
    }
    __syncthreads();

    // ================= Phase 4a: norms + self logits ========================
    for (int i = wid; i < KPG; i += NW) {
        float2 h = HB2[i * 32 + lane];
        float ss = warp_sum(h.x * h.x + h.y * h.y);
        float ni = 1.0f / fmaxf(sqrtf(ss), 1e-12f);
        if (lane == 0) {
            S.ninv[i]   = ni;
            S.scorev[i] = beta * ss * ni * ni;      // logit_s
        }
    }
    __syncthreads();

    // ====== Phase 4b: AGNN online softmax + fused readout ====================
    float2 msum = make_float2(0.f, 0.f);
    float2 mmax = make_float2(-3.4e38f, -3.4e38f);
    for (int i = wid; i < KPG; i += NW) {
        int n = S.klist[i];
        unsigned kb = n ? S.col_off[n - 1] : 0u;
        unsigned ke = kb + S.vcnt[i];
        float ni = S.ninv[i];
        float2 hn = HB2[i * 32 + lane];
        float m     = S.scorev[i];                  // logit_s
        float denom = 1.0f;                         // exp(ls - ls)
        float2 acc  = hn;                           // es * hn with es=1 at start
        for (unsigned k = kb; k < ke; ++k) {
            int rs = S.csr_src[k];
            float2 hs = HB2[rs * 32 + lane];
            float d = warp_sum(fmaf(hn.x, hs.x, hn.y * hs.y));
            float lg = beta * d * ni * S.ninv[rs];
            float mn = fmaxf(m, lg);
            float cr = __expf(m - mn);
            float e2 = __expf(lg - mn);
            denom = fmaf(denom, cr, e2);
            acc.x = fmaf(acc.x, cr, e2 * hs.x);
            acc.y = fmaf(acc.y, cr, e2 * hs.y);
            m = mn;
        }
        float inv = 1.0f / denom;
        float2 o = make_float2(acc.x * inv, acc.y * inv);
        msum.x += o.x;  msum.y += o.y;
        mmax.x = fmaxf(mmax.x, o.x);
        mmax.y = fmaxf(mmax.y, o.y);
    }
    __syncthreads();                                 // csr_src now dead
    {
        float* RS = reinterpret_cast<float*>(S.csr_src);        // [16][64]
        float* RM = RS + NW * F_;                               // [16][64]
        reinterpret_cast<float2*>(RS)[wid * 32 + lane] = msum;
        reinterpret_cast<float2*>(RM)[wid * 32 + lane] = mmax;
        __syncthreads();
        if (tid < F_) {
            float s = 0.f;
            #pragma unroll
            for (int w = 0; w < NW; ++w) s += RS[w * F_ + tid];
            out[(size_t)g * (2 * F_) + tid] = fmaxf(s * (1.0f / (float)KPG), 0.f);
        } else if (tid < 2 * F_) {
            int f = tid - F_;
            float m2 = -3.4e38f;
            #pragma unroll
            for (int w = 0; w < NW; ++w) m2 = fmaxf(m2, RM[w * F_ + f]);
            out[(size_t)g * (2 * F_) + F_ + f] = fmaxf(m2, 0.f);
        }
    }
}

extern "C" void kernel_launch(void* const* d_in, const int* in_sizes, int n_in,
                              void* d_out, int out_size)
{
    const float* x    = (const float*)d_in[0];
    const int*   ei   = (const int*)  d_in[1];
    const float* W1   = (const float*)d_in[2];
    const float* b1   = (const float*)d_in[3];
    const float* beta = (const float*)d_in[4];
    float*       out  = (float*)d_out;

    int smem = (int)sizeof(SmemLayout);
    cudaFuncSetAttribute(gp_fused_kernel,
                         cudaFuncAttributeMaxDynamicSharedMemorySize, smem);
    gp_fused_kernel<<<G_, NTH, smem>>>(x, ei, W1, b1, beta, out);
}